// round 4
// baseline (speedup 1.0000x reference)
#include <cuda_runtime.h>
#include <cuda_fp16.h>

#define M_ROWS 8192
#define N_CLASSES 256
#define DIM 128

// ---------------- scratch (__device__ globals; allocation-free rule) -------
// No persistent accumulators: everything written by plain stores each call.
__device__ __align__(16) __half g_hp[N_CLASSES * DIM];
__device__ __align__(16) __half g_rp[N_CLASSES * DIM];
__device__ __align__(16) float  g_pnp[N_CLASSES * 32];   // partial ||p||^2 [class][chunk]

static __device__ __forceinline__ unsigned smem_u32(const void* p) {
    return (unsigned)__cvta_generic_to_shared(p);
}

#define LDM4(d0, d1, d2, d3, a)                                              \
    asm volatile("ldmatrix.sync.aligned.m8n8.x4.shared.b16 {%0,%1,%2,%3}, [%4];" \
                 : "=r"(d0), "=r"(d1), "=r"(d2), "=r"(d3) : "r"(a))

#define MMA16816(c0, c1, c2, c3, a0, a1, a2, a3, b0, b1)                     \
    asm volatile("mma.sync.aligned.m16n8k16.row.col.f32.f16.f16.f32 "        \
                 "{%0,%1,%2,%3}, {%4,%5,%6,%7}, {%8,%9}, {%0,%1,%2,%3};"     \
                 : "+f"(c0), "+f"(c1), "+f"(c2), "+f"(c3)                    \
                 : "r"(a0), "r"(a1), "r"(a2), "r"(a3), "r"(b0), "r"(b1))

// ---------------------------------------------------------------------------
// k1: fused prototype builder. Grid = 32 CTAs; CTA c4 owns feature dims
// [c4*4, c4*4+4). Smem-local segment-sum (no global atomics, no zero pass),
// then per-class finalize: divide by count, fp16 hi/lo split, partial norm.
// ---------------------------------------------------------------------------
__global__ void __launch_bounds__(256)
proto_kernel(const float* __restrict__ support,
             const int* __restrict__ labels, int S) {
    __shared__ float ssum[N_CLASSES][4];
    __shared__ float scnt[N_CLASSES];

    int tid = threadIdx.x;
    int c4  = blockIdx.x;        // 0..31

    ((float4*)ssum)[tid] = make_float4(0.f, 0.f, 0.f, 0.f);
    scnt[tid] = 0.f;
    __syncthreads();

    for (int r = tid; r < S; r += 256) {
        int lbl = labels[r];
        float4 v = ((const float4*)support)[r * 32 + c4];
        atomicAdd(&ssum[lbl][0], v.x);
        atomicAdd(&ssum[lbl][1], v.y);
        atomicAdd(&ssum[lbl][2], v.z);
        atomicAdd(&ssum[lbl][3], v.w);
        atomicAdd(&scnt[lbl], 1.0f);
    }
    __syncthreads();

    // tid == class id
    float cnt = fmaxf(scnt[tid], 1.0f);
    float v0 = ssum[tid][0] / cnt;
    float v1 = ssum[tid][1] / cnt;
    float v2 = ssum[tid][2] / cnt;
    float v3 = ssum[tid][3] / cnt;

    union { __half2 q[2]; uint2 u; } H, R;
    H.q[0] = __floats2half2_rn(v0, v1);
    H.q[1] = __floats2half2_rn(v2, v3);
    float2 f0 = __half22float2(H.q[0]);
    float2 f1 = __half22float2(H.q[1]);
    R.q[0] = __floats2half2_rn(v0 - f0.x, v1 - f0.y);
    R.q[1] = __floats2half2_rn(v2 - f1.x, v3 - f1.y);

    ((uint2*)(g_hp + (size_t)tid * DIM))[c4] = H.u;
    ((uint2*)(g_rp + (size_t)tid * DIM))[c4] = R.u;
    g_pnp[tid * 32 + c4] = v0 * v0 + v1 * v1 + v2 * v2 + v3 * v3;
}

// ---------------------------------------------------------------------------
// k2: fused convert + tensor-core GEMM.
// out[m][n] = 2*dot(x_m,p_n) - ||x_m||^2 - ||p_n||^2
// dot via fp16 split: h·hp + h·rp + r·hp, f32 accumulators.
// BM=128, BN=128, 256 threads, warp grid 4(m)x2(n), warp tile 32x64.
// x loaded f32 -> converted in-register to h/r smem tiles; ||x||^2 exact f32.
// ||p||^2 reduced from g_pnp partials into smem during the load phase.
// ---------------------------------------------------------------------------
#define BM 128
#define BN 128
#define GEMM_SMEM (4 * BM * DIM * 2 + BM * 4 + BN * 4)

__global__ void __launch_bounds__(256, 1)
mma_kernel(const float* __restrict__ x, float* __restrict__ out) {
    extern __shared__ __half sm[];
    __half* hA = sm;                    // [128][128]
    __half* rA = sm + 16384;
    __half* hB = sm + 32768;            // [128][128]
    __half* rB = sm + 49152;
    float*  xnorm_s = (float*)(sm + 65536);        // [128]
    float*  pnorm_s = (float*)(sm + 65536) + BM;   // [128]

    int tid = threadIdx.x;
    int lane = tid & 31;
    int m0 = blockIdx.x * BM;
    int n0 = blockIdx.y * BN;

    // ---- load x tile (f32), convert to h/r, swizzled smem; ||x||^2 ----
    {
        const float4* gx = (const float4*)(x + (size_t)m0 * DIM);
        uint4* shA = (uint4*)hA;
        uint4* srA = (uint4*)rA;
        #pragma unroll
        for (int i = 0; i < 8; i++) {
            int idx = tid + i * 256;        // 0..2047 (16B chunk id)
            int row = idx >> 4, c = idx & 15;
            float4 v0 = gx[row * 32 + c * 2];
            float4 v1 = gx[row * 32 + c * 2 + 1];

            union { __half2 q[4]; uint4 u; } H, R;
            H.q[0] = __floats2half2_rn(v0.x, v0.y);
            H.q[1] = __floats2half2_rn(v0.z, v0.w);
            H.q[2] = __floats2half2_rn(v1.x, v1.y);
            H.q[3] = __floats2half2_rn(v1.z, v1.w);
            float2 f0 = __half22float2(H.q[0]);
            float2 f1 = __half22float2(H.q[1]);
            float2 f2 = __half22float2(H.q[2]);
            float2 f3 = __half22float2(H.q[3]);
            R.q[0] = __floats2half2_rn(v0.x - f0.x, v0.y - f0.y);
            R.q[1] = __floats2half2_rn(v0.z - f1.x, v0.w - f1.y);
            R.q[2] = __floats2half2_rn(v1.x - f2.x, v1.y - f2.y);
            R.q[3] = __floats2half2_rn(v1.z - f3.x, v1.w - f3.y);

            int sw = c ^ (row & 7);
            shA[row * 16 + sw] = H.u;
            srA[row * 16 + sw] = R.u;

            float s = v0.x * v0.x + v0.y * v0.y + v0.z * v0.z + v0.w * v0.w
                    + v1.x * v1.x + v1.y * v1.y + v1.z * v1.z + v1.w * v1.w;
            #pragma unroll
            for (int o = 1; o < 16; o <<= 1)
                s += __shfl_xor_sync(0xffffffffu, s, o);
            if ((lane & 15) == 0) xnorm_s[row] = s;
        }
    }
    // ---- load prototype tiles (fp16 h/r) + reduce ||p||^2 partials ----
    {
        const uint4* ghB = (const uint4*)(g_hp + (size_t)n0 * DIM);
        const uint4* grB = (const uint4*)(g_rp + (size_t)n0 * DIM);
        uint4* shB = (uint4*)hB;
        uint4* srB = (uint4*)rB;
        #pragma unroll
        for (int i = 0; i < 8; i++) {
            int idx = tid + i * 256;
            int row = idx >> 4, c = idx & 15;
            int sw = c ^ (row & 7);
            shB[row * 16 + sw] = ghB[idx];
            srB[row * 16 + sw] = grB[idx];
        }
        if (tid < BN) {
            const float4* pp = (const float4*)(g_pnp + (size_t)(n0 + tid) * 32);
            float s = 0.f;
            #pragma unroll
            for (int i = 0; i < 8; i++) {
                float4 q = pp[i];
                s += q.x + q.y + q.z + q.w;
            }
            pnorm_s[tid] = s;
        }
    }
    __syncthreads();

    int warp = tid >> 5;
    int wm = warp & 3;        // 0..3  (m, 32 rows each)
    int wn = warp >> 2;       // 0..1  (n, 64 cols each)
    int grp = lane >> 3, lr = lane & 7;

    int rowA[2], keyA[2];
    #pragma unroll
    for (int ms = 0; ms < 2; ms++) {
        rowA[ms] = wm * 32 + ms * 16 + lr + ((grp & 1) << 3);
        keyA[ms] = rowA[ms] & 7;
    }
    int cAadd = grp >> 1;
    int rowB[4], keyB[4];
    #pragma unroll
    for (int np = 0; np < 4; np++) {
        rowB[np] = wn * 64 + np * 16 + lr + ((grp >> 1) << 3);
        keyB[np] = rowB[np] & 7;
    }
    int cBadd = grp & 1;

    unsigned baseHA = smem_u32(hA), baseRA = smem_u32(rA);
    unsigned baseHB = smem_u32(hB), baseRB = smem_u32(rB);
    unsigned offA[2], offB[4];
    #pragma unroll
    for (int i = 0; i < 2; i++) offA[i] = rowA[i] * 256;
    #pragma unroll
    for (int i = 0; i < 4; i++) offB[i] = rowB[i] * 256;

    float acc[2][8][4];
    #pragma unroll
    for (int i = 0; i < 2; i++)
        #pragma unroll
        for (int j = 0; j < 8; j++)
            #pragma unroll
            for (int k = 0; k < 4; k++) acc[i][j][k] = 0.0f;

    #pragma unroll
    for (int ks = 0; ks < 8; ks++) {
        int kc = ks * 2;
        unsigned ah[2][4], ar[2][4], bh[4][4], br[4][4];
        #pragma unroll
        for (int ms = 0; ms < 2; ms++) {
            unsigned sw = ((unsigned)((kc + cAadd) ^ keyA[ms])) << 4;
            LDM4(ah[ms][0], ah[ms][1], ah[ms][2], ah[ms][3], baseHA + offA[ms] + sw);
            LDM4(ar[ms][0], ar[ms][1], ar[ms][2], ar[ms][3], baseRA + offA[ms] + sw);
        }
        #pragma unroll
        for (int np = 0; np < 4; np++) {
            unsigned sw = ((unsigned)((kc + cBadd) ^ keyB[np])) << 4;
            LDM4(bh[np][0], bh[np][1], bh[np][2], bh[np][3], baseHB + offB[np] + sw);
            LDM4(br[np][0], br[np][1], br[np][2], br[np][3], baseRB + offB[np] + sw);
        }
        #pragma unroll
        for (int ms = 0; ms < 2; ms++) {
            #pragma unroll
            for (int ns = 0; ns < 8; ns++) {
                int np = ns >> 1, o = (ns & 1) * 2;
                float* c = acc[ms][ns];
                MMA16816(c[0], c[1], c[2], c[3],
                         ah[ms][0], ah[ms][1], ah[ms][2], ah[ms][3],
                         bh[np][o], bh[np][o + 1]);
                MMA16816(c[0], c[1], c[2], c[3],
                         ah[ms][0], ah[ms][1], ah[ms][2], ah[ms][3],
                         br[np][o], br[np][o + 1]);
                MMA16816(c[0], c[1], c[2], c[3],
                         ar[ms][0], ar[ms][1], ar[ms][2], ar[ms][3],
                         bh[np][o], bh[np][o + 1]);
            }
        }
    }

    // ---- epilogue: out = 2*dot - xnorm - pnorm ----
    int qrow = lane >> 2;
    int qcol = (lane & 3) * 2;
    #pragma unroll
    for (int ms = 0; ms < 2; ms++) {
        int lrow = wm * 32 + ms * 16 + qrow;
        int mrow = m0 + lrow;
        float xn0 = xnorm_s[lrow];
        float xn1 = xnorm_s[lrow + 8];
        #pragma unroll
        for (int ns = 0; ns < 8; ns++) {
            int nl = wn * 64 + ns * 8 + qcol;
            int n  = n0 + nl;
            float pn0 = pnorm_s[nl];
            float pn1 = pnorm_s[nl + 1];
            float* c = acc[ms][ns];
            float2 o0 = make_float2(2.0f * c[0] - xn0 - pn0,
                                    2.0f * c[1] - xn0 - pn1);
            float2 o1 = make_float2(2.0f * c[2] - xn1 - pn0,
                                    2.0f * c[3] - xn1 - pn1);
            *(float2*)&out[(size_t)mrow * N_CLASSES + n] = o0;
            *(float2*)&out[(size_t)(mrow + 8) * N_CLASSES + n] = o1;
        }
    }
}

// ---------------------------------------------------------------------------
extern "C" void kernel_launch(void* const* d_in, const int* in_sizes, int n_in,
                              void* d_out, int out_size) {
    const float* x       = (const float*)d_in[0];
    const float* support = (const float*)d_in[1];
    const int*   labels  = (const int*)d_in[2];
    float* out = (float*)d_out;

    int S = in_sizes[2];  // 4096

    proto_kernel<<<32, 256>>>(support, labels, S);

    cudaFuncSetAttribute(mma_kernel,
                         cudaFuncAttributeMaxDynamicSharedMemorySize, GEMM_SMEM);
    mma_kernel<<<dim3(M_ROWS / BM, N_CLASSES / BN), 256, GEMM_SMEM>>>(x, out);
}

// round 5
// speedup vs baseline: 1.5482x; 1.5482x over previous
#include <cuda_runtime.h>
#include <cuda_fp16.h>

#define M_ROWS 8192
#define N_CLASSES 256
#define DIM 128

// ---------------- scratch (__device__ globals; allocation-free rule) -------
// All written by plain stores every call: no persistent state, no zeroing.
__device__ __align__(16) __half g_hp[N_CLASSES * DIM];
__device__ __align__(16) __half g_rp[N_CLASSES * DIM];
__device__ float g_pnorm[N_CLASSES];

static __device__ __forceinline__ unsigned smem_u32(const void* p) {
    return (unsigned)__cvta_generic_to_shared(p);
}

#define LDM4(d0, d1, d2, d3, a)                                              \
    asm volatile("ldmatrix.sync.aligned.m8n8.x4.shared.b16 {%0,%1,%2,%3}, [%4];" \
                 : "=r"(d0), "=r"(d1), "=r"(d2), "=r"(d3) : "r"(a))

#define MMA16816(c0, c1, c2, c3, a0, a1, a2, a3, b0, b1)                     \
    asm volatile("mma.sync.aligned.m16n8k16.row.col.f32.f16.f16.f32 "        \
                 "{%0,%1,%2,%3}, {%4,%5,%6,%7}, {%8,%9}, {%0,%1,%2,%3};"     \
                 : "+f"(c0), "+f"(c1), "+f"(c2), "+f"(c3)                    \
                 : "r"(a0), "r"(a1), "r"(a2), "r"(a3), "r"(b0), "r"(b1))

// ---------------------------------------------------------------------------
// k1: prototype builder, one CTA per class. No atomics anywhere.
//  1) 256 threads scan labels (16 rows each), deterministic prefix-scan
//     builds the smem index list in row order.
//  2) threads 0..127 each own one dim; gather-sum the listed rows with
//     fully-coalesced 512B row loads, unrolled x4 for MLP.
//  3) finalize: divide by count, fp16 hi/lo split, ||p||^2 shfl-reduce.
// ---------------------------------------------------------------------------
__global__ void __launch_bounds__(256)
proto_kernel(const float* __restrict__ support,
             const int* __restrict__ labels, int S) {
    __shared__ int   list[4096];
    __shared__ int   wbase[9];
    __shared__ float red[4];

    int c    = blockIdx.x;
    int tid  = threadIdx.x;
    int lane = tid & 31;
    int wid  = tid >> 5;

    int per = (S + 255) >> 8;                 // rows per thread (16)
    int r0  = tid * per;
    int r1  = min(r0 + per, S);

    int cnt = 0;
    for (int r = r0; r < r1; r++) cnt += (labels[r] == c);

    // exclusive prefix over 256 threads (warp inclusive scan + smem bases)
    int inc = cnt;
    #pragma unroll
    for (int o = 1; o < 32; o <<= 1) {
        int t = __shfl_up_sync(0xffffffffu, inc, o);
        if (lane >= o) inc += t;
    }
    if (lane == 31) wbase[wid + 1] = inc;
    if (tid == 0) wbase[0] = 0;
    __syncthreads();
    if (tid == 0)
        #pragma unroll
        for (int w = 1; w <= 8; w++) wbase[w] += wbase[w - 1];
    __syncthreads();

    int pos = wbase[wid] + inc - cnt;
    for (int r = r0; r < r1; r++)
        if (labels[r] == c) list[pos++] = r;
    __syncthreads();

    int total = wbase[8];

    if (tid < DIM) {
        float s = 0.0f;
        int i = 0;
        for (; i + 4 <= total; i += 4) {
            float a0 = support[(size_t)list[i + 0] * DIM + tid];
            float a1 = support[(size_t)list[i + 1] * DIM + tid];
            float a2 = support[(size_t)list[i + 2] * DIM + tid];
            float a3 = support[(size_t)list[i + 3] * DIM + tid];
            s += a0; s += a1; s += a2; s += a3;
        }
        for (; i < total; i++)
            s += support[(size_t)list[i] * DIM + tid];

        float cntf = fmaxf((float)total, 1.0f);
        float v = s / cntf;

        __half h = __float2half_rn(v);
        g_hp[c * DIM + tid] = h;
        g_rp[c * DIM + tid] = __float2half_rn(v - __half2float(h));

        float q = v * v;
        #pragma unroll
        for (int o = 16; o > 0; o >>= 1)
            q += __shfl_xor_sync(0xffffffffu, q, o);
        if (lane == 0) red[wid] = q;
    }
    __syncthreads();
    if (tid == 0) g_pnorm[c] = red[0] + red[1] + red[2] + red[3];
}

// ---------------------------------------------------------------------------
// k2: fused convert + tensor-core GEMM (proven round-3 configuration).
// out[m][n] = 2*dot(x_m,p_n) - ||x_m||^2 - ||p_n||^2
// dot via fp16 split: h·hp + h·rp + r·hp, f32 accumulators.
// BM=128, BN=128, 256 threads, warp grid 4(m)x2(n), warp tile 32x64.
// ---------------------------------------------------------------------------
#define BM 128
#define BN 128
#define GEMM_SMEM (4 * BM * DIM * 2 + BM * 4)

__global__ void __launch_bounds__(256, 1)
mma_kernel(const float* __restrict__ x, float* __restrict__ out) {
    extern __shared__ __half sm[];
    __half* hA = sm;                    // [128][128]
    __half* rA = sm + 16384;
    __half* hB = sm + 32768;            // [128][128]
    __half* rB = sm + 49152;
    float*  xnorm_s = (float*)(sm + 65536);   // [128]

    int tid = threadIdx.x;
    int lane = tid & 31;
    int m0 = blockIdx.x * BM;
    int n0 = blockIdx.y * BN;

    // ---- load x tile (f32), convert to h/r, swizzled smem; ||x||^2 ----
    {
        const float4* gx = (const float4*)(x + (size_t)m0 * DIM);
        uint4* shA = (uint4*)hA;
        uint4* srA = (uint4*)rA;
        #pragma unroll
        for (int i = 0; i < 8; i++) {
            int idx = tid + i * 256;        // 16B chunk id
            int row = idx >> 4, c = idx & 15;
            float4 v0 = gx[row * 32 + c * 2];
            float4 v1 = gx[row * 32 + c * 2 + 1];

            union { __half2 q[4]; uint4 u; } H, R;
            H.q[0] = __floats2half2_rn(v0.x, v0.y);
            H.q[1] = __floats2half2_rn(v0.z, v0.w);
            H.q[2] = __floats2half2_rn(v1.x, v1.y);
            H.q[3] = __floats2half2_rn(v1.z, v1.w);
            float2 f0 = __half22float2(H.q[0]);
            float2 f1 = __half22float2(H.q[1]);
            float2 f2 = __half22float2(H.q[2]);
            float2 f3 = __half22float2(H.q[3]);
            R.q[0] = __floats2half2_rn(v0.x - f0.x, v0.y - f0.y);
            R.q[1] = __floats2half2_rn(v0.z - f1.x, v0.w - f1.y);
            R.q[2] = __floats2half2_rn(v1.x - f2.x, v1.y - f2.y);
            R.q[3] = __floats2half2_rn(v1.z - f3.x, v1.w - f3.y);

            int sw = c ^ (row & 7);
            shA[row * 16 + sw] = H.u;
            srA[row * 16 + sw] = R.u;

            float s = v0.x * v0.x + v0.y * v0.y + v0.z * v0.z + v0.w * v0.w
                    + v1.x * v1.x + v1.y * v1.y + v1.z * v1.z + v1.w * v1.w;
            #pragma unroll
            for (int o = 1; o < 16; o <<= 1)
                s += __shfl_xor_sync(0xffffffffu, s, o);
            if ((lane & 15) == 0) xnorm_s[row] = s;
        }
    }
    // ---- load prototype tiles (fp16 h/r) ----
    {
        const uint4* ghB = (const uint4*)(g_hp + (size_t)n0 * DIM);
        const uint4* grB = (const uint4*)(g_rp + (size_t)n0 * DIM);
        uint4* shB = (uint4*)hB;
        uint4* srB = (uint4*)rB;
        #pragma unroll
        for (int i = 0; i < 8; i++) {
            int idx = tid + i * 256;
            int row = idx >> 4, c = idx & 15;
            int sw = c ^ (row & 7);
            shB[row * 16 + sw] = ghB[idx];
            srB[row * 16 + sw] = grB[idx];
        }
    }
    __syncthreads();

    int warp = tid >> 5;
    int wm = warp & 3;        // m, 32 rows each
    int wn = warp >> 2;       // n, 64 cols each
    int grp = lane >> 3, lr = lane & 7;

    int rowA[2], keyA[2];
    #pragma unroll
    for (int ms = 0; ms < 2; ms++) {
        rowA[ms] = wm * 32 + ms * 16 + lr + ((grp & 1) << 3);
        keyA[ms] = rowA[ms] & 7;
    }
    int cAadd = grp >> 1;
    int rowB[4], keyB[4];
    #pragma unroll
    for (int np = 0; np < 4; np++) {
        rowB[np] = wn * 64 + np * 16 + lr + ((grp >> 1) << 3);
        keyB[np] = rowB[np] & 7;
    }
    int cBadd = grp & 1;

    unsigned baseHA = smem_u32(hA), baseRA = smem_u32(rA);
    unsigned baseHB = smem_u32(hB), baseRB = smem_u32(rB);
    unsigned offA[2], offB[4];
    #pragma unroll
    for (int i = 0; i < 2; i++) offA[i] = rowA[i] * 256;
    #pragma unroll
    for (int i = 0; i < 4; i++) offB[i] = rowB[i] * 256;

    float acc[2][8][4];
    #pragma unroll
    for (int i = 0; i < 2; i++)
        #pragma unroll
        for (int j = 0; j < 8; j++)
            #pragma unroll
            for (int k = 0; k < 4; k++) acc[i][j][k] = 0.0f;

    #pragma unroll
    for (int ks = 0; ks < 8; ks++) {
        int kc = ks * 2;
        unsigned ah[2][4], ar[2][4], bh[4][4], br[4][4];
        #pragma unroll
        for (int ms = 0; ms < 2; ms++) {
            unsigned sw = ((unsigned)((kc + cAadd) ^ keyA[ms])) << 4;
            LDM4(ah[ms][0], ah[ms][1], ah[ms][2], ah[ms][3], baseHA + offA[ms] + sw);
            LDM4(ar[ms][0], ar[ms][1], ar[ms][2], ar[ms][3], baseRA + offA[ms] + sw);
        }
        #pragma unroll
        for (int np = 0; np < 4; np++) {
            unsigned sw = ((unsigned)((kc + cBadd) ^ keyB[np])) << 4;
            LDM4(bh[np][0], bh[np][1], bh[np][2], bh[np][3], baseHB + offB[np] + sw);
            LDM4(br[np][0], br[np][1], br[np][2], br[np][3], baseRB + offB[np] + sw);
        }
        #pragma unroll
        for (int ms = 0; ms < 2; ms++) {
            #pragma unroll
            for (int ns = 0; ns < 8; ns++) {
                int np = ns >> 1, o = (ns & 1) * 2;
                float* c = acc[ms][ns];
                MMA16816(c[0], c[1], c[2], c[3],
                         ah[ms][0], ah[ms][1], ah[ms][2], ah[ms][3],
                         bh[np][o], bh[np][o + 1]);
                MMA16816(c[0], c[1], c[2], c[3],
                         ah[ms][0], ah[ms][1], ah[ms][2], ah[ms][3],
                         br[np][o], br[np][o + 1]);
                MMA16816(c[0], c[1], c[2], c[3],
                         ar[ms][0], ar[ms][1], ar[ms][2], ar[ms][3],
                         bh[np][o], bh[np][o + 1]);
            }
        }
    }

    // ---- epilogue: out = 2*dot - xnorm - pnorm ----
    int qrow = lane >> 2;
    int qcol = (lane & 3) * 2;
    #pragma unroll
    for (int ms = 0; ms < 2; ms++) {
        int lrow = wm * 32 + ms * 16 + qrow;
        int mrow = m0 + lrow;
        float xn0 = xnorm_s[lrow];
        float xn1 = xnorm_s[lrow + 8];
        #pragma unroll
        for (int ns = 0; ns < 8; ns++) {
            int n = n0 + wn * 64 + ns * 8 + qcol;
            float pn0 = __ldg(&g_pnorm[n]);
            float pn1 = __ldg(&g_pnorm[n + 1]);
            float* c = acc[ms][ns];
            float2 o0 = make_float2(2.0f * c[0] - xn0 - pn0,
                                    2.0f * c[1] - xn0 - pn1);
            float2 o1 = make_float2(2.0f * c[2] - xn1 - pn0,
                                    2.0f * c[3] - xn1 - pn1);
            *(float2*)&out[(size_t)mrow * N_CLASSES + n] = o0;
            *(float2*)&out[(size_t)(mrow + 8) * N_CLASSES + n] = o1;
        }
    }
}

// ---------------------------------------------------------------------------
extern "C" void kernel_launch(void* const* d_in, const int* in_sizes, int n_in,
                              void* d_out, int out_size) {
    const float* x       = (const float*)d_in[0];
    const float* support = (const float*)d_in[1];
    const int*   labels  = (const int*)d_in[2];
    float* out = (float*)d_out;

    int S = in_sizes[2];  // 4096

    proto_kernel<<<N_CLASSES, 256>>>(support, labels, S);

    cudaFuncSetAttribute(mma_kernel,
                         cudaFuncAttributeMaxDynamicSharedMemorySize, GEMM_SMEM);
    mma_kernel<<<dim3(M_ROWS / BM, N_CLASSES / BN), 256, GEMM_SMEM>>>(x, out);
}

// round 6
// speedup vs baseline: 1.7362x; 1.1214x over previous
#include <cuda_runtime.h>
#include <cuda_fp16.h>

#define M_ROWS 8192
#define N_CLASSES 256
#define DIM 128

// ---------------- scratch (__device__ globals; allocation-free rule) -------
__device__ __align__(16) __half g_hp[N_CLASSES * DIM];
__device__ float g_pnorm[N_CLASSES];

static __device__ __forceinline__ unsigned smem_u32(const void* p) {
    return (unsigned)__cvta_generic_to_shared(p);
}

#define LDM4(d0, d1, d2, d3, a)                                              \
    asm volatile("ldmatrix.sync.aligned.m8n8.x4.shared.b16 {%0,%1,%2,%3}, [%4];" \
                 : "=r"(d0), "=r"(d1), "=r"(d2), "=r"(d3) : "r"(a))

#define MMA16816(c0, c1, c2, c3, a0, a1, a2, a3, b0, b1)                     \
    asm volatile("mma.sync.aligned.m16n8k16.row.col.f32.f16.f16.f32 "        \
                 "{%0,%1,%2,%3}, {%4,%5,%6,%7}, {%8,%9}, {%0,%1,%2,%3};"     \
                 : "+f"(c0), "+f"(c1), "+f"(c2), "+f"(c3)                    \
                 : "r"(a0), "r"(a1), "r"(a2), "r"(a3), "r"(b0), "r"(b1))

// ---------------------------------------------------------------------------
// k1: prototype builder, one CTA per class. No atomics.
// ---------------------------------------------------------------------------
__global__ void __launch_bounds__(256)
proto_kernel(const float* __restrict__ support,
             const int* __restrict__ labels, int S) {
    __shared__ int   list[4096];
    __shared__ int   wbase[9];
    __shared__ float red[4];

    int c    = blockIdx.x;
    int tid  = threadIdx.x;
    int lane = tid & 31;
    int wid  = tid >> 5;

    int per = (S + 255) >> 8;
    int r0  = tid * per;
    int r1  = min(r0 + per, S);

    int cnt = 0;
    #pragma unroll 4
    for (int r = r0; r < r1; r++) cnt += (labels[r] == c);

    int inc = cnt;
    #pragma unroll
    for (int o = 1; o < 32; o <<= 1) {
        int t = __shfl_up_sync(0xffffffffu, inc, o);
        if (lane >= o) inc += t;
    }
    if (lane == 31) wbase[wid + 1] = inc;
    if (tid == 0) wbase[0] = 0;
    __syncthreads();
    if (tid == 0)
        #pragma unroll
        for (int w = 1; w <= 8; w++) wbase[w] += wbase[w - 1];
    __syncthreads();

    int pos = wbase[wid] + inc - cnt;
    for (int r = r0; r < r1; r++)
        if (labels[r] == c) list[pos++] = r;
    __syncthreads();

    int total = wbase[8];

    if (tid < DIM) {
        float s = 0.0f;
        int i = 0;
        for (; i + 4 <= total; i += 4) {
            float a0 = support[(size_t)list[i + 0] * DIM + tid];
            float a1 = support[(size_t)list[i + 1] * DIM + tid];
            float a2 = support[(size_t)list[i + 2] * DIM + tid];
            float a3 = support[(size_t)list[i + 3] * DIM + tid];
            s += a0; s += a1; s += a2; s += a3;
        }
        for (; i < total; i++)
            s += support[(size_t)list[i] * DIM + tid];

        float cntf = fmaxf((float)total, 1.0f);
        float v = s / cntf;

        g_hp[c * DIM + tid] = __float2half_rn(v);

        float q = v * v;
        #pragma unroll
        for (int o = 16; o > 0; o >>= 1)
            q += __shfl_xor_sync(0xffffffffu, q, o);
        if (lane == 0) red[wid] = q;
    }
    __syncthreads();
    if (tid == 0) g_pnorm[c] = red[0] + red[1] + red[2] + red[3];
}

// ---------------------------------------------------------------------------
// k2: fused convert + fp16 tensor-core GEMM.
// out[m][n] = 2*dot(x_m,p_n) - ||x_m||^2 - ||p_n||^2   (plain fp16 dot)
// BM=64, BN=128, 256 threads, warp grid 2(m)x4(n), warp tile 32x32.
// grid = 128 x 2 = 256 CTAs, smem ~49KB -> 2 CTAs/SM.
// ---------------------------------------------------------------------------
#define BM 64
#define BN 128
#define GEMM_SMEM (BM * DIM * 2 + BN * DIM * 2 + BM * 4)   // 49408

__global__ void __launch_bounds__(256, 2)
mma_kernel(const float* __restrict__ x, float* __restrict__ out) {
    extern __shared__ __half sm[];
    __half* hA = sm;                    // [64][128]
    __half* hB = sm + BM * DIM;         // [128][128]
    float*  xnorm_s = (float*)(sm + BM * DIM + BN * DIM);   // [64]

    int tid = threadIdx.x;
    int lane = tid & 31;
    int m0 = blockIdx.x * BM;
    int n0 = blockIdx.y * BN;

    // ---- load x tile (f32), convert to fp16, swizzled smem; ||x||^2 ----
    {
        const float4* gx = (const float4*)(x + (size_t)m0 * DIM);
        uint4* shA = (uint4*)hA;
        #pragma unroll
        for (int i = 0; i < 4; i++) {
            int idx = tid + i * 256;        // 0..1023 (16B fp16 chunk id)
            int row = idx >> 4, c = idx & 15;
            float4 v0 = gx[row * 32 + c * 2];
            float4 v1 = gx[row * 32 + c * 2 + 1];

            union { __half2 q[4]; uint4 u; } H;
            H.q[0] = __floats2half2_rn(v0.x, v0.y);
            H.q[1] = __floats2half2_rn(v0.z, v0.w);
            H.q[2] = __floats2half2_rn(v1.x, v1.y);
            H.q[3] = __floats2half2_rn(v1.z, v1.w);

            int sw = c ^ (row & 7);
            shA[row * 16 + sw] = H.u;

            float s = v0.x * v0.x + v0.y * v0.y + v0.z * v0.z + v0.w * v0.w
                    + v1.x * v1.x + v1.y * v1.y + v1.z * v1.z + v1.w * v1.w;
            #pragma unroll
            for (int o = 1; o < 16; o <<= 1)
                s += __shfl_xor_sync(0xffffffffu, s, o);
            if ((lane & 15) == 0) xnorm_s[row] = s;
        }
    }
    // ---- load prototype tile (fp16) ----
    {
        const uint4* ghB = (const uint4*)(g_hp + (size_t)n0 * DIM);
        uint4* shB = (uint4*)hB;
        #pragma unroll
        for (int i = 0; i < 8; i++) {
            int idx = tid + i * 256;
            int row = idx >> 4, c = idx & 15;
            int sw = c ^ (row & 7);
            shB[row * 16 + sw] = ghB[idx];
        }
    }
    __syncthreads();

    int warp = tid >> 5;
    int wm = warp & 1;        // m, 32 rows each
    int wn = warp >> 1;       // n, 32 cols each
    int grp = lane >> 3, lr = lane & 7;

    int rowA[2], keyA[2];
    #pragma unroll
    for (int ms = 0; ms < 2; ms++) {
        rowA[ms] = wm * 32 + ms * 16 + lr + ((grp & 1) << 3);
        keyA[ms] = rowA[ms] & 7;
    }
    int cAadd = grp >> 1;
    int rowB[2], keyB[2];
    #pragma unroll
    for (int np = 0; np < 2; np++) {
        rowB[np] = wn * 32 + np * 16 + lr + ((grp >> 1) << 3);
        keyB[np] = rowB[np] & 7;
    }
    int cBadd = grp & 1;

    unsigned baseHA = smem_u32(hA);
    unsigned baseHB = smem_u32(hB);
    unsigned offA[2], offB[2];
    #pragma unroll
    for (int i = 0; i < 2; i++) { offA[i] = rowA[i] * 256; offB[i] = rowB[i] * 256; }

    float acc[2][4][4];
    #pragma unroll
    for (int i = 0; i < 2; i++)
        #pragma unroll
        for (int j = 0; j < 4; j++)
            #pragma unroll
            for (int k = 0; k < 4; k++) acc[i][j][k] = 0.0f;

    #pragma unroll
    for (int ks = 0; ks < 8; ks++) {
        int kc = ks * 2;
        unsigned ah[2][4], bh[2][4];
        #pragma unroll
        for (int ms = 0; ms < 2; ms++) {
            unsigned sw = ((unsigned)((kc + cAadd) ^ keyA[ms])) << 4;
            LDM4(ah[ms][0], ah[ms][1], ah[ms][2], ah[ms][3], baseHA + offA[ms] + sw);
        }
        #pragma unroll
        for (int np = 0; np < 2; np++) {
            unsigned sw = ((unsigned)((kc + cBadd) ^ keyB[np])) << 4;
            LDM4(bh[np][0], bh[np][1], bh[np][2], bh[np][3], baseHB + offB[np] + sw);
        }
        #pragma unroll
        for (int ms = 0; ms < 2; ms++) {
            #pragma unroll
            for (int ns = 0; ns < 4; ns++) {
                int np = ns >> 1, o = (ns & 1) * 2;
                float* c = acc[ms][ns];
                MMA16816(c[0], c[1], c[2], c[3],
                         ah[ms][0], ah[ms][1], ah[ms][2], ah[ms][3],
                         bh[np][o], bh[np][o + 1]);
            }
        }
    }

    // ---- epilogue: out = 2*dot - xnorm - pnorm ----
    int qrow = lane >> 2;
    int qcol = (lane & 3) * 2;
    #pragma unroll
    for (int ms = 0; ms < 2; ms++) {
        int lrow = wm * 32 + ms * 16 + qrow;
        int mrow = m0 + lrow;
        float xn0 = xnorm_s[lrow];
        float xn1 = xnorm_s[lrow + 8];
        #pragma unroll
        for (int ns = 0; ns < 4; ns++) {
            int n = n0 + wn * 32 + ns * 8 + qcol;
            float pn0 = __ldg(&g_pnorm[n]);
            float pn1 = __ldg(&g_pnorm[n + 1]);
            float* c = acc[ms][ns];
            float2 o0 = make_float2(2.0f * c[0] - xn0 - pn0,
                                    2.0f * c[1] - xn0 - pn1);
            float2 o1 = make_float2(2.0f * c[2] - xn1 - pn0,
                                    2.0f * c[3] - xn1 - pn1);
            *(float2*)&out[(size_t)mrow * N_CLASSES + n] = o0;
            *(float2*)&out[(size_t)(mrow + 8) * N_CLASSES + n] = o1;
        }
    }
}

// ---------------------------------------------------------------------------
extern "C" void kernel_launch(void* const* d_in, const int* in_sizes, int n_in,
                              void* d_out, int out_size) {
    const float* x       = (const float*)d_in[0];
    const float* support = (const float*)d_in[1];
    const int*   labels  = (const int*)d_in[2];
    float* out = (float*)d_out;

    int S = in_sizes[2];  // 4096

    proto_kernel<<<N_CLASSES, 256>>>(support, labels, S);

    cudaFuncSetAttribute(mma_kernel,
                         cudaFuncAttributeMaxDynamicSharedMemorySize, GEMM_SMEM);
    mma_kernel<<<dim3(M_ROWS / BM, N_CLASSES / BN), 256, GEMM_SMEM>>>(x, out);
}

// round 7
// speedup vs baseline: 1.9427x; 1.1189x over previous
#include <cuda_runtime.h>
#include <cuda_fp16.h>

#define M_ROWS 8192
#define N_CLASSES 256
#define DIM 128

// ---------------- scratch (__device__ globals; allocation-free rule) -------
__device__ __align__(16) __half g_hp[N_CLASSES * DIM];
__device__ float g_pnorm[N_CLASSES];

static __device__ __forceinline__ unsigned smem_u32(const void* p) {
    return (unsigned)__cvta_generic_to_shared(p);
}

#define LDM4(d0, d1, d2, d3, a)                                              \
    asm volatile("ldmatrix.sync.aligned.m8n8.x4.shared.b16 {%0,%1,%2,%3}, [%4];" \
                 : "=r"(d0), "=r"(d1), "=r"(d2), "=r"(d3) : "r"(a))

#define MMA16816(c0, c1, c2, c3, a0, a1, a2, a3, b0, b1)                     \
    asm volatile("mma.sync.aligned.m16n8k16.row.col.f32.f16.f16.f32 "        \
                 "{%0,%1,%2,%3}, {%4,%5,%6,%7}, {%8,%9}, {%0,%1,%2,%3};"     \
                 : "+f"(c0), "+f"(c1), "+f"(c2), "+f"(c3)                    \
                 : "r"(a0), "r"(a1), "r"(a2), "r"(a3), "r"(b0), "r"(b1))

#define CP_ASYNC16(dst, src)                                                 \
    asm volatile("cp.async.cg.shared.global [%0], [%1], 16;"                 \
                 :: "r"(dst), "l"(src))

// ---------------------------------------------------------------------------
// k1: prototype builder, one CTA per class. No atomics, everything coalesced.
//  1) 256 threads scan labels with r = tid + i*256 (coalesced); prefix-scan
//     builds a deterministic smem index list.
//  2) 256-thread gather: thread = (dim, half); each half sums alternate list
//     entries (stride 2, unroll 4); halves combined via smem (deterministic).
//  3) finalize: divide by count, fp16 store, ||p||^2 shfl-reduce.
// ---------------------------------------------------------------------------
__global__ void __launch_bounds__(256)
proto_kernel(const float* __restrict__ support,
             const int* __restrict__ labels, int S) {
    __shared__ int   list[4096];
    __shared__ int   wbase[9];
    __shared__ float part[2][DIM];
    __shared__ float red[4];

    int c    = blockIdx.x;
    int tid  = threadIdx.x;
    int lane = tid & 31;
    int wid  = tid >> 5;

    int nIter = (S + 255) >> 8;     // 16

    int cnt = 0;
    #pragma unroll 4
    for (int i = 0; i < nIter; i++) {
        int r = tid + i * 256;
        if (r < S) cnt += (labels[r] == c);
    }

    // exclusive prefix over 256 threads
    int inc = cnt;
    #pragma unroll
    for (int o = 1; o < 32; o <<= 1) {
        int t = __shfl_up_sync(0xffffffffu, inc, o);
        if (lane >= o) inc += t;
    }
    if (lane == 31) wbase[wid + 1] = inc;
    if (tid == 0) wbase[0] = 0;
    __syncthreads();
    if (tid == 0)
        #pragma unroll
        for (int w = 1; w <= 8; w++) wbase[w] += wbase[w - 1];
    __syncthreads();

    int pos = wbase[wid] + inc - cnt;
    for (int i = 0; i < nIter; i++) {
        int r = tid + i * 256;
        if (r < S && labels[r] == c) list[pos++] = r;
    }
    __syncthreads();

    int total = wbase[8];

    // 256-thread gather: (dim, half)
    {
        int d    = tid & 127;
        int half = tid >> 7;
        float s = 0.0f;
        int i = half;
        for (; i + 6 < total; i += 8) {
            float a0 = support[(size_t)list[i]     * DIM + d];
            float a1 = support[(size_t)list[i + 2] * DIM + d];
            float a2 = support[(size_t)list[i + 4] * DIM + d];
            float a3 = support[(size_t)list[i + 6] * DIM + d];
            s += a0; s += a1; s += a2; s += a3;
        }
        for (; i < total; i += 2)
            s += support[(size_t)list[i] * DIM + d];
        part[half][d] = s;
    }
    __syncthreads();

    if (tid < DIM) {
        float cntf = fmaxf((float)total, 1.0f);
        float v = (part[0][tid] + part[1][tid]) / cntf;
        g_hp[c * DIM + tid] = __float2half_rn(v);

        float q = v * v;
        #pragma unroll
        for (int o = 16; o > 0; o >>= 1)
            q += __shfl_xor_sync(0xffffffffu, q, o);
        if (lane == 0) red[wid] = q;
    }
    __syncthreads();
    if (tid == 0) g_pnorm[c] = red[0] + red[1] + red[2] + red[3];
}

// ---------------------------------------------------------------------------
// k2: fused convert + fp16 tensor-core GEMM.
// out[m][n] = 2*dot(x_m,p_n) - ||x_m||^2 - ||p_n||^2
// BM=64, BN=128, 256 threads, warp grid 2(m)x4(n), warp tile 32x32.
// grid = 128 x 2 = 256 CTAs, 2 CTAs/SM.
// B tile via cp.async (overlapped under A load/convert); xnorm via smem
// partials (no shfl chains in the load path); pnorm preloaded to smem.
// ---------------------------------------------------------------------------
#define BM 64
#define BN 128
// hA 16384B + hB 32768B + xpart 64*17*4 + xnorm 64*4 + pnorm 128*4
#define GEMM_SMEM (BM * DIM * 2 + BN * DIM * 2 + 64 * 17 * 4 + 64 * 4 + 128 * 4)

__global__ void __launch_bounds__(256, 2)
mma_kernel(const float* __restrict__ x, float* __restrict__ out) {
    extern __shared__ __half sm[];
    __half* hA = sm;                          // [64][128]
    __half* hB = sm + BM * DIM;               // [128][128]
    float*  xpart   = (float*)(sm + BM * DIM + BN * DIM);   // [64][17]
    float*  xnorm_s = xpart + 64 * 17;                      // [64]
    float*  pnorm_s = xnorm_s + 64;                         // [128]

    int tid = threadIdx.x;
    int lane = tid & 31;
    int m0 = blockIdx.x * BM;
    int n0 = blockIdx.y * BN;

    // ---- B tile via cp.async (issued first, hides under A loads) ----
    {
        const uint4* ghB = (const uint4*)(g_hp + (size_t)n0 * DIM);
        unsigned sB = smem_u32(hB);
        #pragma unroll
        for (int i = 0; i < 8; i++) {
            int idx = tid + i * 256;
            int row = idx >> 4, c = idx & 15;
            int sw = c ^ (row & 7);
            CP_ASYNC16(sB + (unsigned)(row * 16 + sw) * 16, ghB + idx);
        }
        asm volatile("cp.async.commit_group;");
    }
    if (tid < BN) pnorm_s[tid] = g_pnorm[n0 + tid];

    // ---- load x tile (f32), convert to fp16, swizzled smem; xnorm partials ----
    {
        const float4* gx = (const float4*)(x + (size_t)m0 * DIM);
        uint4* shA = (uint4*)hA;
        #pragma unroll
        for (int i = 0; i < 4; i++) {
            int idx = tid + i * 256;        // 16B fp16 chunk id
            int row = idx >> 4, c = idx & 15;
            float4 v0 = gx[row * 32 + c * 2];
            float4 v1 = gx[row * 32 + c * 2 + 1];

            union { __half2 q[4]; uint4 u; } H;
            H.q[0] = __floats2half2_rn(v0.x, v0.y);
            H.q[1] = __floats2half2_rn(v0.z, v0.w);
            H.q[2] = __floats2half2_rn(v1.x, v1.y);
            H.q[3] = __floats2half2_rn(v1.z, v1.w);

            int sw = c ^ (row & 7);
            shA[row * 16 + sw] = H.u;

            xpart[row * 17 + c] =
                  v0.x * v0.x + v0.y * v0.y + v0.z * v0.z + v0.w * v0.w
                + v1.x * v1.x + v1.y * v1.y + v1.z * v1.z + v1.w * v1.w;
        }
    }
    asm volatile("cp.async.wait_group 0;");
    __syncthreads();

    // xnorm reduce (64 threads; consumed after the post-MMA sync)
    if (tid < BM) {
        float s = 0.0f;
        #pragma unroll
        for (int c = 0; c < 16; c++) s += xpart[tid * 17 + c];
        xnorm_s[tid] = s;
    }

    int warp = tid >> 5;
    int wm = warp & 1;        // m, 32 rows each
    int wn = warp >> 1;       // n, 32 cols each
    int grp = lane >> 3, lr = lane & 7;

    int rowA[2], keyA[2];
    #pragma unroll
    for (int ms = 0; ms < 2; ms++) {
        rowA[ms] = wm * 32 + ms * 16 + lr + ((grp & 1) << 3);
        keyA[ms] = rowA[ms] & 7;
    }
    int cAadd = grp >> 1;
    int rowB[2], keyB[2];
    #pragma unroll
    for (int np = 0; np < 2; np++) {
        rowB[np] = wn * 32 + np * 16 + lr + ((grp >> 1) << 3);
        keyB[np] = rowB[np] & 7;
    }
    int cBadd = grp & 1;

    unsigned baseHA = smem_u32(hA);
    unsigned baseHB = smem_u32(hB);
    unsigned offA[2], offB[2];
    #pragma unroll
    for (int i = 0; i < 2; i++) { offA[i] = rowA[i] * 256; offB[i] = rowB[i] * 256; }

    float acc[2][4][4];
    #pragma unroll
    for (int i = 0; i < 2; i++)
        #pragma unroll
        for (int j = 0; j < 4; j++)
            #pragma unroll
            for (int k = 0; k < 4; k++) acc[i][j][k] = 0.0f;

    #pragma unroll
    for (int ks = 0; ks < 8; ks++) {
        int kc = ks * 2;
        unsigned ah[2][4], bh[2][4];
        #pragma unroll
        for (int ms = 0; ms < 2; ms++) {
            unsigned sw = ((unsigned)((kc + cAadd) ^ keyA[ms])) << 4;
            LDM4(ah[ms][0], ah[ms][1], ah[ms][2], ah[ms][3], baseHA + offA[ms] + sw);
        }
        #pragma unroll
        for (int np = 0; np < 2; np++) {
            unsigned sw = ((unsigned)((kc + cBadd) ^ keyB[np])) << 4;
            LDM4(bh[np][0], bh[np][1], bh[np][2], bh[np][3], baseHB + offB[np] + sw);
        }
        #pragma unroll
        for (int ms = 0; ms < 2; ms++) {
            #pragma unroll
            for (int ns = 0; ns < 4; ns++) {
                int np = ns >> 1, o = (ns & 1) * 2;
                float* c = acc[ms][ns];
                MMA16816(c[0], c[1], c[2], c[3],
                         ah[ms][0], ah[ms][1], ah[ms][2], ah[ms][3],
                         bh[np][o], bh[np][o + 1]);
            }
        }
    }
    __syncthreads();   // xnorm_s ready for all threads

    // ---- epilogue: out = 2*dot - xnorm - pnorm ----
    int qrow = lane >> 2;
    int qcol = (lane & 3) * 2;
    #pragma unroll
    for (int ms = 0; ms < 2; ms++) {
        int lrow = wm * 32 + ms * 16 + qrow;
        int mrow = m0 + lrow;
        float xn0 = xnorm_s[lrow];
        float xn1 = xnorm_s[lrow + 8];
        #pragma unroll
        for (int ns = 0; ns < 4; ns++) {
            int nl = wn * 32 + ns * 8 + qcol;
            int n  = n0 + nl;
            float pn0 = pnorm_s[nl];
            float pn1 = pnorm_s[nl + 1];
            float* c = acc[ms][ns];
            float2 o0 = make_float2(2.0f * c[0] - xn0 - pn0,
                                    2.0f * c[1] - xn0 - pn1);
            float2 o1 = make_float2(2.0f * c[2] - xn1 - pn0,
                                    2.0f * c[3] - xn1 - pn1);
            *(float2*)&out[(size_t)mrow * N_CLASSES + n] = o0;
            *(float2*)&out[(size_t)(mrow + 8) * N_CLASSES + n] = o1;
        }
    }
}

// ---------------------------------------------------------------------------
extern "C" void kernel_launch(void* const* d_in, const int* in_sizes, int n_in,
                              void* d_out, int out_size) {
    const float* x       = (const float*)d_in[0];
    const float* support = (const float*)d_in[1];
    const int*   labels  = (const int*)d_in[2];
    float* out = (float*)d_out;

    int S = in_sizes[2];  // 4096

    proto_kernel<<<N_CLASSES, 256>>>(support, labels, S);

    cudaFuncSetAttribute(mma_kernel,
                         cudaFuncAttributeMaxDynamicSharedMemorySize, GEMM_SMEM);
    mma_kernel<<<dim3(M_ROWS / BM, N_CLASSES / BN), 256, GEMM_SMEM>>>(x, out);
}

// round 8
// speedup vs baseline: 2.2932x; 1.1805x over previous
#include <cuda_runtime.h>
#include <cuda_fp16.h>

#define M_ROWS 8192
#define N_CLASSES 256
#define DIM 128

// ---------------- scratch (__device__ globals; allocation-free rule) -------
__device__ __align__(16) __half g_hp[N_CLASSES * DIM];
__device__ float g_pnorm[N_CLASSES];

static __device__ __forceinline__ unsigned smem_u32(const void* p) {
    return (unsigned)__cvta_generic_to_shared(p);
}

#define LDM4(d0, d1, d2, d3, a)                                              \
    asm volatile("ldmatrix.sync.aligned.m8n8.x4.shared.b16 {%0,%1,%2,%3}, [%4];" \
                 : "=r"(d0), "=r"(d1), "=r"(d2), "=r"(d3) : "r"(a))

#define MMA16816(c0, c1, c2, c3, a0, a1, a2, a3, b0, b1)                     \
    asm volatile("mma.sync.aligned.m16n8k16.row.col.f32.f16.f16.f32 "        \
                 "{%0,%1,%2,%3}, {%4,%5,%6,%7}, {%8,%9}, {%0,%1,%2,%3};"     \
                 : "+f"(c0), "+f"(c1), "+f"(c2), "+f"(c3)                    \
                 : "r"(a0), "r"(a1), "r"(a2), "r"(a3), "r"(b0), "r"(b1))

#define CP_ASYNC16(dst, src)                                                 \
    asm volatile("cp.async.cg.shared.global [%0], [%1], 16;"                 \
                 :: "r"(dst), "l"(src))

// ---------------------------------------------------------------------------
// k1: prototype builder, one CTA per class. No atomics; int4-vectorized
// label scans (both passes), coalesced gather.
// ---------------------------------------------------------------------------
__global__ void __launch_bounds__(256)
proto_kernel(const float* __restrict__ support,
             const int* __restrict__ labels, int S) {
    __shared__ int   list[4096];
    __shared__ int   wbase[9];
    __shared__ float part[2][DIM];
    __shared__ float red[4];

    int c    = blockIdx.x;
    int tid  = threadIdx.x;
    int lane = tid & 31;
    int wid  = tid >> 5;

    const int4* L4 = (const int4*)labels;
    int n4 = S >> 2;                       // 1024 (S divisible by 4)
    int nIter = (n4 + 255) >> 8;           // 4

    int cnt = 0;
    #pragma unroll
    for (int i = 0; i < 4; i++) {
        if (i >= nIter) break;
        int idx = tid + i * 256;
        if (idx < n4) {
            int4 v = __ldg(&L4[idx]);
            cnt += (v.x == c) + (v.y == c) + (v.z == c) + (v.w == c);
        }
    }

    // exclusive prefix over 256 threads
    int inc = cnt;
    #pragma unroll
    for (int o = 1; o < 32; o <<= 1) {
        int t = __shfl_up_sync(0xffffffffu, inc, o);
        if (lane >= o) inc += t;
    }
    if (lane == 31) wbase[wid + 1] = inc;
    if (tid == 0) wbase[0] = 0;
    __syncthreads();
    if (tid == 0)
        #pragma unroll
        for (int w = 1; w <= 8; w++) wbase[w] += wbase[w - 1];
    __syncthreads();

    int pos = wbase[wid] + inc - cnt;
    #pragma unroll
    for (int i = 0; i < 4; i++) {
        if (i >= nIter) break;
        int idx = tid + i * 256;
        if (idx < n4) {
            int4 v = __ldg(&L4[idx]);
            int r = idx * 4;
            if (v.x == c) list[pos++] = r;
            if (v.y == c) list[pos++] = r + 1;
            if (v.z == c) list[pos++] = r + 2;
            if (v.w == c) list[pos++] = r + 3;
        }
    }
    __syncthreads();

    int total = wbase[8];

    // 256-thread gather: (dim, half), stride-2 unroll-4
    {
        int d    = tid & 127;
        int half = tid >> 7;
        float s = 0.0f;
        int i = half;
        for (; i + 6 < total; i += 8) {
            float a0 = __ldg(&support[(size_t)list[i]     * DIM + d]);
            float a1 = __ldg(&support[(size_t)list[i + 2] * DIM + d]);
            float a2 = __ldg(&support[(size_t)list[i + 4] * DIM + d]);
            float a3 = __ldg(&support[(size_t)list[i + 6] * DIM + d]);
            s += a0; s += a1; s += a2; s += a3;
        }
        for (; i < total; i += 2)
            s += __ldg(&support[(size_t)list[i] * DIM + d]);
        part[half][d] = s;
    }
    __syncthreads();

    if (tid < DIM) {
        float cntf = fmaxf((float)total, 1.0f);
        float v = (part[0][tid] + part[1][tid]) / cntf;
        g_hp[c * DIM + tid] = __float2half_rn(v);

        float q = v * v;
        #pragma unroll
        for (int o = 16; o > 0; o >>= 1)
            q += __shfl_xor_sync(0xffffffffu, q, o);
        if (lane == 0) red[wid] = q;
    }
    __syncthreads();
    if (tid == 0) g_pnorm[c] = red[0] + red[1] + red[2] + red[3];
}

// ---------------------------------------------------------------------------
// k2: fused convert + fp16 tensor-core GEMM.
// out[m][n] = 2*dot(x_m,p_n) - ||x_m||^2 - ||p_n||^2
// BM=BN=64, 128 threads (4 warps, 2x2, warp tile 32x32).
// grid = 128 x 4 = 512 CTAs, ~37KB smem -> 5 CTAs/SM (high occupancy).
// ---------------------------------------------------------------------------
#define BM 64
#define BN 64
// hA 16KB + hB 16KB + xpart 64*17*4 + xnorm 64*4 + pnorm 64*4
#define GEMM_SMEM (BM * DIM * 2 + BN * DIM * 2 + 64 * 17 * 4 + 64 * 4 + 64 * 4)

__global__ void __launch_bounds__(128)
mma_kernel(const float* __restrict__ x, float* __restrict__ out) {
    extern __shared__ __half sm[];
    __half* hA = sm;                          // [64][128]
    __half* hB = sm + BM * DIM;               // [64][128]
    float*  xpart   = (float*)(sm + BM * DIM + BN * DIM);   // [64][17]
    float*  xnorm_s = xpart + 64 * 17;                      // [64]
    float*  pnorm_s = xnorm_s + 64;                         // [64]

    int tid = threadIdx.x;
    int lane = tid & 31;
    int m0 = blockIdx.x * BM;
    int n0 = blockIdx.y * BN;

    // ---- B tile via cp.async (issued first, hides under A loads) ----
    {
        const uint4* ghB = (const uint4*)(g_hp + (size_t)n0 * DIM);
        unsigned sB = smem_u32(hB);
        #pragma unroll
        for (int i = 0; i < 8; i++) {
            int idx = tid + i * 128;
            int row = idx >> 4, c = idx & 15;
            int sw = c ^ (row & 7);
            CP_ASYNC16(sB + (unsigned)(row * 16 + sw) * 16, ghB + idx);
        }
        asm volatile("cp.async.commit_group;");
    }
    if (tid < BN) pnorm_s[tid] = g_pnorm[n0 + tid];

    // ---- load x tile (f32), convert to fp16, swizzled smem; xnorm partials ----
    {
        const float4* gx = (const float4*)(x + (size_t)m0 * DIM);
        uint4* shA = (uint4*)hA;
        #pragma unroll
        for (int i = 0; i < 8; i++) {
            int idx = tid + i * 128;        // 16B fp16 chunk id
            int row = idx >> 4, c = idx & 15;
            float4 v0 = gx[row * 32 + c * 2];
            float4 v1 = gx[row * 32 + c * 2 + 1];

            union { __half2 q[4]; uint4 u; } H;
            H.q[0] = __floats2half2_rn(v0.x, v0.y);
            H.q[1] = __floats2half2_rn(v0.z, v0.w);
            H.q[2] = __floats2half2_rn(v1.x, v1.y);
            H.q[3] = __floats2half2_rn(v1.z, v1.w);

            int sw = c ^ (row & 7);
            shA[row * 16 + sw] = H.u;

            xpart[row * 17 + c] =
                  v0.x * v0.x + v0.y * v0.y + v0.z * v0.z + v0.w * v0.w
                + v1.x * v1.x + v1.y * v1.y + v1.z * v1.z + v1.w * v1.w;
        }
    }
    asm volatile("cp.async.wait_group 0;");
    __syncthreads();

    // xnorm reduce (64 threads; consumed after the post-MMA sync)
    if (tid < BM) {
        float s = 0.0f;
        #pragma unroll
        for (int c = 0; c < 16; c++) s += xpart[tid * 17 + c];
        xnorm_s[tid] = s;
    }

    int warp = tid >> 5;
    int wm = warp & 1;        // m, 32 rows each
    int wn = warp >> 1;       // n, 32 cols each
    int grp = lane >> 3, lr = lane & 7;

    int rowA[2], keyA[2];
    #pragma unroll
    for (int ms = 0; ms < 2; ms++) {
        rowA[ms] = wm * 32 + ms * 16 + lr + ((grp & 1) << 3);
        keyA[ms] = rowA[ms] & 7;
    }
    int cAadd = grp >> 1;
    int rowB[2], keyB[2];
    #pragma unroll
    for (int np = 0; np < 2; np++) {
        rowB[np] = wn * 32 + np * 16 + lr + ((grp >> 1) << 3);
        keyB[np] = rowB[np] & 7;
    }
    int cBadd = grp & 1;

    unsigned baseHA = smem_u32(hA);
    unsigned baseHB = smem_u32(hB);
    unsigned offA[2], offB[2];
    #pragma unroll
    for (int i = 0; i < 2; i++) { offA[i] = rowA[i] * 256; offB[i] = rowB[i] * 256; }

    float acc[2][4][4];
    #pragma unroll
    for (int i = 0; i < 2; i++)
        #pragma unroll
        for (int j = 0; j < 4; j++)
            #pragma unroll
            for (int k = 0; k < 4; k++) acc[i][j][k] = 0.0f;

    #pragma unroll
    for (int ks = 0; ks < 8; ks++) {
        int kc = ks * 2;
        unsigned ah[2][4], bh[2][4];
        #pragma unroll
        for (int ms = 0; ms < 2; ms++) {
            unsigned sw = ((unsigned)((kc + cAadd) ^ keyA[ms])) << 4;
            LDM4(ah[ms][0], ah[ms][1], ah[ms][2], ah[ms][3], baseHA + offA[ms] + sw);
        }
        #pragma unroll
        for (int np = 0; np < 2; np++) {
            unsigned sw = ((unsigned)((kc + cBadd) ^ keyB[np])) << 4;
            LDM4(bh[np][0], bh[np][1], bh[np][2], bh[np][3], baseHB + offB[np] + sw);
        }
        #pragma unroll
        for (int ms = 0; ms < 2; ms++) {
            #pragma unroll
            for (int ns = 0; ns < 4; ns++) {
                int np = ns >> 1, o = (ns & 1) * 2;
                float* c = acc[ms][ns];
                MMA16816(c[0], c[1], c[2], c[3],
                         ah[ms][0], ah[ms][1], ah[ms][2], ah[ms][3],
                         bh[np][o], bh[np][o + 1]);
            }
        }
    }
    __syncthreads();   // xnorm_s ready for all threads

    // ---- epilogue: out = 2*dot - xnorm - pnorm ----
    int qrow = lane >> 2;
    int qcol = (lane & 3) * 2;
    #pragma unroll
    for (int ms = 0; ms < 2; ms++) {
        int lrow = wm * 32 + ms * 16 + qrow;
        int mrow = m0 + lrow;
        float xn0 = xnorm_s[lrow];
        float xn1 = xnorm_s[lrow + 8];
        #pragma unroll
        for (int ns = 0; ns < 4; ns++) {
            int nl = wn * 32 + ns * 8 + qcol;
            int n  = n0 + nl;
            float pn0 = pnorm_s[nl];
            float pn1 = pnorm_s[nl + 1];
            float* c = acc[ms][ns];
            float2 o0 = make_float2(2.0f * c[0] - xn0 - pn0,
                                    2.0f * c[1] - xn0 - pn1);
            float2 o1 = make_float2(2.0f * c[2] - xn1 - pn0,
                                    2.0f * c[3] - xn1 - pn1);
            *(float2*)&out[(size_t)mrow * N_CLASSES + n] = o0;
            *(float2*)&out[(size_t)(mrow + 8) * N_CLASSES + n] = o1;
        }
    }
}

// ---------------------------------------------------------------------------
extern "C" void kernel_launch(void* const* d_in, const int* in_sizes, int n_in,
                              void* d_out, int out_size) {
    const float* x       = (const float*)d_in[0];
    const float* support = (const float*)d_in[1];
    const int*   labels  = (const int*)d_in[2];
    float* out = (float*)d_out;

    int S = in_sizes[2];  // 4096

    proto_kernel<<<N_CLASSES, 256>>>(support, labels, S);

    cudaFuncSetAttribute(mma_kernel,
                         cudaFuncAttributeMaxDynamicSharedMemorySize, GEMM_SMEM);
    mma_kernel<<<dim3(M_ROWS / BM, N_CLASSES / BN), 128, GEMM_SMEM>>>(x, out);
}